// round 15
// baseline (speedup 1.0000x reference)
#include <cuda_runtime.h>
#include <math.h>

#define BTOT   65536
#define DIN    256
#define HDIM   64
#define ADIM   32
#define NACT   14
#define NS     8
#define BM     64
#define PO     68        // row-major pitch (Abuf, x_r, h_r)
#define PT     68        // feature-major pitch (qkv_s)
#define PHO    100       // ho_r row pitch
#define NTHREADS 256

typedef unsigned long long ull;

// ---- fragment tables, 32B-granular: [nt][lane][ksGroup][8 floats] ----
__device__ __align__(128) float g_encF[8 * 32 * 8 * 8];     // KG=8 (ks 0..31)
__device__ __align__(128) float g_gruF[24 * 32 * 4 * 8];    // KG=4 (ks 0..15)
__device__ __align__(128) float g_qkvF[12 * 32 * 2 * 8];    // KG=2 (ks 0..7)
__device__ __align__(16)  float g_decP[NACT * 96];          // [c][k]

__device__ __forceinline__ unsigned to_tf32(float x) {
    unsigned r; asm("cvt.rna.tf32.f32 %0, %1;" : "=r"(r) : "f"(x)); return r;
}

__global__ void setup_kernel(const float* __restrict__ encW,
                             const float* __restrict__ Wih,
                             const float* __restrict__ Whh,
                             const float* __restrict__ qW,
                             const float* __restrict__ kW,
                             const float* __restrict__ vW,
                             const float* __restrict__ decW)
{
    const int stride = gridDim.x * blockDim.x;
    const int t0 = blockIdx.x * blockDim.x + threadIdx.x;

    // encF: idx = ((nt*32+lane)*8 + kg)*8 + ksin*2 + p
    for (int idx = t0; idx < 8 * 32 * 8 * 8; idx += stride) {
        int j = idx & 7, p = j & 1, ksin = j >> 1;
        int t = idx >> 3, kg = t & 7;
        int t2 = t >> 3, lane = t2 & 31, nt = t2 >> 5;
        int ks = kg * 4 + ksin;
        int krow = ks * 8 + (lane & 3) + 4 * p;       // 0..255
        int col  = nt * 8 + (lane >> 2);              // 0..63
        g_encF[idx] = __uint_as_float(to_tf32(encW[krow * HDIM + col]));
    }
    // gruF: KG=4; ks 0..15 (0..7 = Wih k, 8..15 = Whh k)
    for (int idx = t0; idx < 24 * 32 * 4 * 8; idx += stride) {
        int j = idx & 7, p = j & 1, ksin = j >> 1;
        int t = idx >> 3, kg = t & 3;
        int t2 = t >> 2, lane = t2 & 31, nt = t2 >> 5;
        int ks = kg * 4 + ksin;
        int krow = ks * 8 + (lane & 3) + 4 * p;       // 0..127
        int col  = nt * 8 + (lane >> 2);              // 0..191
        float v = (krow < 64) ? Wih[col * HDIM + krow] : Whh[col * HDIM + (krow - 64)];
        g_gruF[idx] = __uint_as_float(to_tf32(v));
    }
    // qkvF: KG=2; ks 0..7
    for (int idx = t0; idx < 12 * 32 * 2 * 8; idx += stride) {
        int j = idx & 7, p = j & 1, ksin = j >> 1;
        int t = idx >> 3, kg = t & 1;
        int t2 = t >> 1, lane = t2 & 31, nt = t2 >> 5;
        int ks = kg * 4 + ksin;
        int krow = ks * 8 + (lane & 3) + 4 * p;       // 0..63
        int col  = nt * 8 + (lane >> 2);              // 0..95
        float v;
        if (col < 32)      v = qW[krow * 32 + col];
        else if (col < 64) v = kW[krow * 32 + (col - 32)];
        else               v = vW[krow * 32 + (col - 64)];
        g_qkvF[idx] = __uint_as_float(to_tf32(v));
    }
    for (int idx = t0; idx < NACT * 96; idx += stride) {
        int c = idx / 96, k = idx - c * 96;
        g_decP[idx] = decW[k * NACT + c];
    }
}

// ---------------- helpers ----------------
__device__ __forceinline__ void ffma2(ull& acc, ull a, ull b) {
    asm("fma.rn.f32x2 %0, %1, %2, %0;" : "+l"(acc) : "l"(a), "l"(b));
}
__device__ __forceinline__ ull pack2(float x) {
    ull d; unsigned xi = __float_as_uint(x);
    asm("mov.b64 %0, {%1, %1};" : "=l"(d) : "r"(xi));
    return d;
}
__device__ __forceinline__ ull pack_ab(float a, float b) {
    ull d;
    asm("mov.b64 %0, {%1, %2};" : "=l"(d) : "f"(a), "f"(b));
    return d;
}
__device__ __forceinline__ float2 unpack2(ull v) {
    float2 r;
    asm("mov.b64 {%0, %1}, %2;" : "=f"(r.x), "=f"(r.y) : "l"(v));
    return r;
}
__device__ __forceinline__ float hsum2(ull v) { float2 r = unpack2(v); return r.x + r.y; }
__device__ __forceinline__ unsigned saddr(const void* p) {
    return (unsigned)__cvta_generic_to_shared(p);
}
__device__ __forceinline__ float tanh_fast(float x) {
    float r; asm("tanh.approx.f32 %0, %1;" : "=f"(r) : "f"(x)); return r;
}
__device__ __forceinline__ float sigmoid_fast(float s) {
    return fmaf(tanh_fast(0.5f * s), 0.5f, 0.5f);
}
// 32B fragment load, L2-pinned
__device__ __forceinline__ void ldg256_evl(const float* p, unsigned* r) {
    asm("ld.global.nc.L2::evict_last.v8.b32 {%0,%1,%2,%3,%4,%5,%6,%7}, [%8];"
        : "=r"(r[0]), "=r"(r[1]), "=r"(r[2]), "=r"(r[3]),
          "=r"(r[4]), "=r"(r[5]), "=r"(r[6]), "=r"(r[7])
        : "l"(p));
}
__device__ __forceinline__ void mma_tf32(float* d,
                                         unsigned a0, unsigned a1, unsigned a2, unsigned a3,
                                         unsigned b0, unsigned b1) {
    asm("mma.sync.aligned.m16n8k8.row.col.f32.tf32.tf32.f32 "
        "{%0,%1,%2,%3}, {%4,%5,%6,%7}, {%8,%9}, {%0,%1,%2,%3};"
        : "+f"(d[0]), "+f"(d[1]), "+f"(d[2]), "+f"(d[3])
        : "r"(a0), "r"(a1), "r"(a2), "r"(a3), "r"(b0), "r"(b1));
}
__device__ __forceinline__ void ldsm_x4(unsigned& a0, unsigned& a1, unsigned& a2, unsigned& a3,
                                        unsigned addr) {
    asm volatile("ldmatrix.sync.aligned.m8n8.x4.shared.b16 {%0,%1,%2,%3}, [%4];"
        : "=r"(a0), "=r"(a1), "=r"(a2), "=r"(a3) : "r"(addr));
}

// single n-tile, 4 m-tile, 8 ks; frag loads = 2x LDG.256 (evict_last)
__device__ __forceinline__ void mma_pass1(const float* __restrict__ src, int pitch,
                                          const float* __restrict__ frag, int KG,
                                          int kgBase, int fnt,
                                          int lane, float* acc)
{
    const int rsel = lane & 15;
    const int csel = (lane & 16) ? 4 : 0;
    const float* fb = &frag[(size_t)((fnt * 32 + lane) * KG + kgBase) * 8];
#pragma unroll
    for (int kc = 0; kc < 8; kc += 4) {
        unsigned fr[8];
        ldg256_evl(fb + (kc >> 2) * 8, fr);
#pragma unroll
        for (int ks = 0; ks < 4; ks++) {
            const int kcol = (kc + ks) * 8 + csel;
#pragma unroll
            for (int mt = 0; mt < 4; mt++) {
                unsigned a0, a1, a2, a3;
                ldsm_x4(a0, a1, a2, a3, saddr(&src[(mt * 16 + rsel) * pitch + kcol]));
                mma_tf32(acc + mt * 4, a0, a1, a2, a3, fr[ks * 2], fr[ks * 2 + 1]);
            }
        }
    }
}

// DUAL n-tile pass: A-fragments loaded once, feed two accumulator sets
__device__ __forceinline__ void mma_passD(const float* __restrict__ src, int pitch,
                                          const float* __restrict__ frag, int KG,
                                          int kgBase, int fnt0, int fnt1,
                                          int lane, float* accA, float* accB)
{
    const int rsel = lane & 15;
    const int csel = (lane & 16) ? 4 : 0;
    const float* fbA = &frag[(size_t)((fnt0 * 32 + lane) * KG + kgBase) * 8];
    const float* fbB = &frag[(size_t)((fnt1 * 32 + lane) * KG + kgBase) * 8];
#pragma unroll
    for (int kc = 0; kc < 8; kc += 4) {
        unsigned frA[8], frB[8];
        ldg256_evl(fbA + (kc >> 2) * 8, frA);
        ldg256_evl(fbB + (kc >> 2) * 8, frB);
#pragma unroll
        for (int ks = 0; ks < 4; ks++) {
            const int kcol = (kc + ks) * 8 + csel;
#pragma unroll
            for (int mt = 0; mt < 4; mt++) {
                unsigned a0, a1, a2, a3;
                ldsm_x4(a0, a1, a2, a3, saddr(&src[(mt * 16 + rsel) * pitch + kcol]));
                mma_tf32(accA + mt * 4, a0, a1, a2, a3, frA[ks * 2], frA[ks * 2 + 1]);
                mma_tf32(accB + mt * 4, a0, a1, a2, a3, frB[ks * 2], frB[ks * 2 + 1]);
            }
        }
    }
}

__global__ void __launch_bounds__(NTHREADS, 3)
fused_kernel(const float* __restrict__ obs,
             const float* __restrict__ hid,
             const float* __restrict__ encb,
             const float* __restrict__ bih,
             const float* __restrict__ bhh,
             const float* __restrict__ vb,
             const float* __restrict__ decb,
             float* __restrict__ outp,
             float* __restrict__ houtp)
{
    extern __shared__ float sm[];
    // regionA [0, 8704): obs double buffer -> later ho_r (64 x PHO = 6400)
    float* Abuf0 = sm;
    float* Abuf1 = sm + 4352;
    float* ho_r  = sm;                 // [64 rows][PHO]
    // regionB [8704, 17408): x_r + h_r -> later qkv_s (96 x PT = 6528) + out_s (896)
    float* x_r   = sm + 8704;          // [64 rows][PO]
    float* h_r   = sm + 13056;         // [64 rows][PO]
    float* qkv_s = sm + 8704;          // [96 feat][PT]
    float* out_s = sm + 8704 + 6528;   // [64 rows][14]

    const int tid  = threadIdx.x;
    const int w    = tid >> 5;
    const int lane = tid & 31;
    const int g    = lane >> 2;
    const int tg   = lane & 3;
    const int rowbase = blockIdx.x * BM;

    // ---- prefetch obs tile 0 via cp.async ----
    {
#pragma unroll
        for (int c = 0; c < 4; c++) {
            int chunk = tid + c * 256;
            int row = chunk >> 4, off = (chunk & 15) * 4;
            const float* src = obs + (size_t)(rowbase + row) * DIN + off;
            unsigned d = saddr(&Abuf0[row * PO + off]);
            asm volatile("cp.async.cg.shared.global [%0], [%1], 16;" :: "r"(d), "l"(src));
        }
        asm volatile("cp.async.commit_group;");
    }

    // ---- load hidden_state row-major ----
    for (int v = tid; v < BM * 16; v += NTHREADS) {
        int r = v >> 4, c4 = (v & 15) * 4;
        *reinterpret_cast<float4*>(&h_r[r * PO + c4]) =
            *reinterpret_cast<const float4*>(&hid[(size_t)(rowbase + r) * HDIM + c4]);
    }

    // ---------------- encoder via tf32 mma: warp w owns n-tile w, 64 rows ----
    {
        float d[16];
#pragma unroll
        for (int e = 0; e < 16; e++) d[e] = 0.f;

#pragma unroll
        for (int kt = 0; kt < 4; kt++) {
            __syncthreads();
            if (kt < 3) {
                float* dst = ((kt + 1) & 1) ? Abuf1 : Abuf0;
#pragma unroll
                for (int c = 0; c < 4; c++) {
                    int chunk = tid + c * 256;
                    int row = chunk >> 4, off = (chunk & 15) * 4;
                    const float* src = obs + (size_t)(rowbase + row) * DIN + (kt + 1) * 64 + off;
                    unsigned dsta = saddr(&dst[row * PO + off]);
                    asm volatile("cp.async.cg.shared.global [%0], [%1], 16;" :: "r"(dsta), "l"(src));
                }
                asm volatile("cp.async.commit_group;");
                asm volatile("cp.async.wait_group 1;");
            } else {
                asm volatile("cp.async.wait_group 0;");
            }
            __syncthreads();

            const float* Ac = (kt & 1) ? Abuf1 : Abuf0;
            mma_pass1(Ac, PO, g_encF, 8, kt * 2, w, lane, d);
        }

        const int col0 = w * 8 + tg * 2;
        const float b0 = encb[col0], b1 = encb[col0 + 1];
#pragma unroll
        for (int mt = 0; mt < 4; mt++) {
            const int row0 = mt * 16 + g;
            const float* am = d + mt * 4;
            *reinterpret_cast<ull*>(&x_r[row0 * PO + col0]) =
                pack_ab(fmaxf(am[0] + b0, 0.f), fmaxf(am[1] + b1, 0.f));
            *reinterpret_cast<ull*>(&x_r[(row0 + 8) * PO + col0]) =
                pack_ab(fmaxf(am[2] + b0, 0.f), fmaxf(am[3] + b1, 0.f));
        }
    }
    __syncthreads();

    // ---------------- GRU via tf32 mma, dual-acc r/z sweeps ----------------
    {
        const int col0 = w * 8 + tg * 2;
        float accR[16], accZ[16];
#pragma unroll
        for (int e = 0; e < 16; e++) { accR[e] = 0.f; accZ[e] = 0.f; }

        mma_passD(x_r, PO, g_gruF, 4, 0, w, 8 + w, lane, accR, accZ);
        mma_passD(h_r, PO, g_gruF, 4, 2, w, 8 + w, lane, accR, accZ);

        // r = sigmoid(accR + biases)
        {
            const float2 b1 = *reinterpret_cast<const float2*>(&bih[col0]);
            const float2 b2 = *reinterpret_cast<const float2*>(&bhh[col0]);
            const float bx = b1.x + b2.x, by = b1.y + b2.y;
#pragma unroll
            for (int mt = 0; mt < 4; mt++) {
                float* a = accR + mt * 4;
                a[0] = sigmoid_fast(a[0] + bx);
                a[1] = sigmoid_fast(a[1] + by);
                a[2] = sigmoid_fast(a[2] + bx);
                a[3] = sigmoid_fast(a[3] + by);
            }
        }
        // hn: accR = r * (h@Un + bhh_n)
        {
            float accN[16];
#pragma unroll
            for (int e = 0; e < 16; e++) accN[e] = 0.f;
            mma_pass1(h_r, PO, g_gruF, 4, 2, 16 + w, lane, accN);
            const float2 b2 = *reinterpret_cast<const float2*>(&bhh[128 + col0]);
#pragma unroll
            for (int mt = 0; mt < 4; mt++) {
                float* a = accN + mt * 4;
                float* c = accR + mt * 4;
                c[0] *= (a[0] + b2.x); c[1] *= (a[1] + b2.y);
                c[2] *= (a[2] + b2.x); c[3] *= (a[3] + b2.y);
            }
        }
        // xn: accR = tanh(x@Wn + bih_n + accR)
        {
            float accN[16];
#pragma unroll
            for (int e = 0; e < 16; e++) accN[e] = 0.f;
            mma_pass1(x_r, PO, g_gruF, 4, 0, 16 + w, lane, accN);
            const float2 b1 = *reinterpret_cast<const float2*>(&bih[128 + col0]);
#pragma unroll
            for (int mt = 0; mt < 4; mt++) {
                float* a = accN + mt * 4;
                float* c = accR + mt * 4;
                c[0] = tanh_fast(a[0] + b1.x + c[0]);
                c[1] = tanh_fast(a[1] + b1.y + c[1]);
                c[2] = tanh_fast(a[2] + b1.x + c[2]);
                c[3] = tanh_fast(a[3] + b1.y + c[3]);
            }
        }
        // z (from accZ) + blend + store ho_r
        {
            const float2 b1 = *reinterpret_cast<const float2*>(&bih[64 + col0]);
            const float2 b2 = *reinterpret_cast<const float2*>(&bhh[64 + col0]);
            const float bx = b1.x + b2.x, by = b1.y + b2.y;
#pragma unroll
            for (int mt = 0; mt < 4; mt++) {
                float* a = accZ + mt * 4;
                float* n = accR + mt * 4;
                const int rA = mt * 16 + g, rB = rA + 8;
                float z0 = sigmoid_fast(a[0] + bx);
                float z1 = sigmoid_fast(a[1] + by);
                float z2 = sigmoid_fast(a[2] + bx);
                float z3 = sigmoid_fast(a[3] + by);
                const float2 hA = *reinterpret_cast<const float2*>(&h_r[rA * PO + col0]);
                const float2 hB = *reinterpret_cast<const float2*>(&h_r[rB * PO + col0]);
                *reinterpret_cast<ull*>(&ho_r[rA * PHO + col0]) =
                    pack_ab((1.f - z0) * n[0] + z0 * hA.x, (1.f - z1) * n[1] + z1 * hA.y);
                *reinterpret_cast<ull*>(&ho_r[rB * PHO + col0]) =
                    pack_ab((1.f - z2) * n[2] + z2 * hB.x, (1.f - z3) * n[3] + z3 * hB.y);
            }
        }
    }
    __syncthreads();

    // ---------------- h_out writeback + QKV via tf32 mma --------------------
    {
        for (int v = tid; v < BM * 16; v += NTHREADS) {
            int r = v >> 4, c4 = (v & 15) * 4;
            *reinterpret_cast<float4*>(&houtp[(size_t)(rowbase + r) * HDIM + c4]) =
                *reinterpret_cast<const float4*>(&ho_r[r * PHO + c4]);
        }

        float acc1[16], acc2[16];
#pragma unroll
        for (int e = 0; e < 16; e++) { acc1[e] = 0.f; acc2[e] = 0.f; }
        if (w < 4) {
            mma_passD(ho_r, PHO, g_qkvF, 2, 0, w, 8 + w, lane, acc1, acc2);
        } else {
            mma_pass1(ho_r, PHO, g_qkvF, 2, 0, w, lane, acc1);
        }

        __syncthreads();   // x_r/h_r fully dead before qkv_s overlay writes

        {
            const int col0 = w * 8 + tg * 2;   // 0..63 (q|k): no bias/relu
#pragma unroll
            for (int mt = 0; mt < 4; mt++) {
                const int rA = mt * 16 + g, rB = rA + 8;
                float* a = acc1 + mt * 4;
                qkv_s[col0 * PT + rA]       = a[0];
                qkv_s[(col0 + 1) * PT + rA] = a[1];
                qkv_s[col0 * PT + rB]       = a[2];
                qkv_s[(col0 + 1) * PT + rB] = a[3];
            }
        }
        if (w < 4) {
            const int col0 = 64 + w * 8 + tg * 2;   // v cols: bias + relu
            const float b0 = vb[col0 - 64], b1 = vb[col0 - 63];
#pragma unroll
            for (int mt = 0; mt < 4; mt++) {
                const int rA = mt * 16 + g, rB = rA + 8;
                float* a = acc2 + mt * 4;
                qkv_s[col0 * PT + rA]       = fmaxf(a[0] + b0, 0.f);
                qkv_s[(col0 + 1) * PT + rA] = fmaxf(a[1] + b1, 0.f);
                qkv_s[col0 * PT + rB]       = fmaxf(a[2] + b0, 0.f);
                qkv_s[(col0 + 1) * PT + rB] = fmaxf(a[3] + b1, 0.f);
            }
        }
    }
    __syncthreads();

    // ---------------- exclude-self attention (packed over j-pairs) ----------
    if (tid < BM) {
        const int ii = tid & 7;
        const int base = tid & ~7;
        ull sp[4] = {0, 0, 0, 0};
#pragma unroll 8
        for (int a = 0; a < ADIM; a++) {
            ull qa = pack2(qkv_s[a * PT + tid]);
            const ulonglong2 k01 = *reinterpret_cast<const ulonglong2*>(&qkv_s[(32 + a) * PT + base]);
            const ulonglong2 k23 = *reinterpret_cast<const ulonglong2*>(&qkv_s[(32 + a) * PT + base + 4]);
            ffma2(sp[0], k01.x, qa); ffma2(sp[1], k01.y, qa);
            ffma2(sp[2], k23.x, qa); ffma2(sp[3], k23.y, qa);
        }
        float sc[NS];
#pragma unroll
        for (int jp = 0; jp < 4; jp++) {
            float2 v = unpack2(sp[jp]);
            sc[2 * jp]     = v.x * 0.17677669529663689f;
            sc[2 * jp + 1] = v.y * 0.17677669529663689f;
        }
        sc[ii] = -1e9f;
        float mx = -1e30f;
#pragma unroll
        for (int j = 0; j < NS; j++) mx = fmaxf(mx, sc[j]);
        float sum = 0.f;
#pragma unroll
        for (int j = 0; j < NS; j++) { sc[j] = __expf(sc[j] - mx); sum += sc[j]; }
        const float inv = __fdividef(1.f, sum);
        ull wp[4];
#pragma unroll
        for (int jp = 0; jp < 4; jp++)
            wp[jp] = pack_ab(sc[2 * jp] * inv, sc[2 * jp + 1] * inv);
        float xa[ADIM];
#pragma unroll 8
        for (int a = 0; a < ADIM; a++) {
            const ulonglong2 v01 = *reinterpret_cast<const ulonglong2*>(&qkv_s[(64 + a) * PT + base]);
            const ulonglong2 v23 = *reinterpret_cast<const ulonglong2*>(&qkv_s[(64 + a) * PT + base + 4]);
            ull t = 0;
            ffma2(t, v01.x, wp[0]); ffma2(t, v01.y, wp[1]);
            ffma2(t, v23.x, wp[2]); ffma2(t, v23.y, wp[3]);
            xa[a] = hsum2(t);
        }
#pragma unroll
        for (int a4 = 0; a4 < 8; a4++) {
            float4 o = make_float4(xa[a4 * 4], xa[a4 * 4 + 1], xa[a4 * 4 + 2], xa[a4 * 4 + 3]);
            *reinterpret_cast<float4*>(&ho_r[tid * PHO + 64 + a4 * 4]) = o;
        }
    }
    __syncthreads();

    // ---------------- decoder -> out_s (smem), then coalesced store ---------
    for (int it = tid; it < 448; it += NTHREADS) {
        int pr = it & 31, c = it >> 5;
        const float* hA = &ho_r[(2 * pr) * PHO];
        const float* hB = &ho_r[(2 * pr + 1) * PHO];
        ull acc0 = 0, acc1 = 0;
#pragma unroll 6
        for (int k4 = 0; k4 < 24; k4++) {
            const ulonglong2 wv = *reinterpret_cast<const ulonglong2*>(&g_decP[c * 96 + k4 * 4]);
            const ulonglong2 a4 = *reinterpret_cast<const ulonglong2*>(&hA[k4 * 4]);
            const ulonglong2 b4 = *reinterpret_cast<const ulonglong2*>(&hB[k4 * 4]);
            ffma2(acc0, a4.x, wv.x); ffma2(acc0, a4.y, wv.y);
            ffma2(acc1, b4.x, wv.x); ffma2(acc1, b4.y, wv.y);
        }
        float b = decb[c];
        out_s[(2 * pr) * NACT + c]     = hsum2(acc0) + b;
        out_s[(2 * pr + 1) * NACT + c] = hsum2(acc1) + b;
    }
    __syncthreads();
    {
        float4* dst = reinterpret_cast<float4*>(outp + (size_t)rowbase * NACT);
        const float4* src = reinterpret_cast<const float4*>(out_s);
        for (int v = tid; v < (BM * NACT) / 4; v += NTHREADS)
            dst[v] = src[v];
    }
}

extern "C" void kernel_launch(void* const* d_in, const int* in_sizes, int n_in,
                              void* d_out, int out_size)
{
    (void)in_sizes; (void)n_in; (void)out_size;
    const float* obs  = (const float*)d_in[0];
    const float* hid  = (const float*)d_in[1];
    const float* encW = (const float*)d_in[2];
    const float* encb = (const float*)d_in[3];
    const float* Wih  = (const float*)d_in[4];
    const float* Whh  = (const float*)d_in[5];
    const float* bih  = (const float*)d_in[6];
    const float* bhh  = (const float*)d_in[7];
    const float* qW   = (const float*)d_in[8];
    const float* kW   = (const float*)d_in[9];
    const float* vW   = (const float*)d_in[10];
    const float* vb   = (const float*)d_in[11];
    const float* decW = (const float*)d_in[12];
    const float* decb = (const float*)d_in[13];

    float* outp  = (float*)d_out;                 // [B, 14]
    float* houtp = outp + (size_t)BTOT * NACT;    // [B, 64]

    setup_kernel<<<64, 256>>>(encW, Wih, Whh, qW, kW, vW, decW);

    const int smem_bytes = 17408 * sizeof(float); // 69,632 B -> 3 CTAs/SM
    cudaFuncSetAttribute(fused_kernel,
                         cudaFuncAttributeMaxDynamicSharedMemorySize, smem_bytes);
    fused_kernel<<<BTOT / BM, NTHREADS, smem_bytes>>>(
        obs, hid, encb, bih, bhh, vb, decb, outp, houtp);
}

// round 16
// speedup vs baseline: 1.2543x; 1.2543x over previous
#include <cuda_runtime.h>
#include <math.h>

#define BTOT   65536
#define DIN    256
#define HDIM   64
#define ADIM   32
#define NACT   14
#define NS     8
#define BM     64
#define PO     68        // row-major pitch (Abuf, x_r, h_r)
#define PT     68        // feature-major pitch (qkv_s)
#define PHO    100       // ho_r row pitch
#define NTHREADS 256

typedef unsigned long long ull;

// ---- persistent fragment-packed tf32 weights + decoder weights ----
__device__ __align__(16) float g_encF[32 * 8 * 64];    // [ks][nt][lane][2]
__device__ __align__(16) float g_gruF[16 * 24 * 64];   // [ks][nt][lane][2]
__device__ __align__(16) float g_qkvF[8 * 12 * 64];    // [ks][nt][lane][2]
__device__ __align__(16) float g_decP[NACT * 96];      // [c][k]

__device__ __forceinline__ unsigned to_tf32(float x) {
    unsigned r; asm("cvt.rna.tf32.f32 %0, %1;" : "=r"(r) : "f"(x)); return r;
}

__global__ void setup_kernel(const float* __restrict__ encW,
                             const float* __restrict__ Wih,
                             const float* __restrict__ Whh,
                             const float* __restrict__ qW,
                             const float* __restrict__ kW,
                             const float* __restrict__ vW,
                             const float* __restrict__ decW)
{
    const int stride = gridDim.x * blockDim.x;
    const int t0 = blockIdx.x * blockDim.x + threadIdx.x;

    for (int idx = t0; idx < 32 * 8 * 64; idx += stride) {
        int p = idx & 1, lane = (idx >> 1) & 31;
        int rest = idx >> 6;
        int nt = rest & 7, ks = rest >> 3;
        int krow = ks * 8 + (lane & 3) + 4 * p;
        int col  = nt * 8 + (lane >> 2);
        g_encF[idx] = __uint_as_float(to_tf32(encW[krow * HDIM + col]));
    }
    for (int idx = t0; idx < 16 * 24 * 64; idx += stride) {
        int p = idx & 1, lane = (idx >> 1) & 31;
        int rest = idx >> 6;
        int nt = rest % 24, ks = rest / 24;
        int krow = ks * 8 + (lane & 3) + 4 * p;   // 0..127
        int col  = nt * 8 + (lane >> 2);          // 0..191
        float v = (krow < 64) ? Wih[col * HDIM + krow] : Whh[col * HDIM + (krow - 64)];
        g_gruF[idx] = __uint_as_float(to_tf32(v));
    }
    for (int idx = t0; idx < 8 * 12 * 64; idx += stride) {
        int p = idx & 1, lane = (idx >> 1) & 31;
        int rest = idx >> 6;
        int nt = rest % 12, ks = rest / 12;
        int krow = ks * 8 + (lane & 3) + 4 * p;   // 0..63
        int col  = nt * 8 + (lane >> 2);          // 0..95
        float v;
        if (col < 32)      v = qW[krow * 32 + col];
        else if (col < 64) v = kW[krow * 32 + (col - 32)];
        else               v = vW[krow * 32 + (col - 64)];
        g_qkvF[idx] = __uint_as_float(to_tf32(v));
    }
    for (int idx = t0; idx < NACT * 96; idx += stride) {
        int c = idx / 96, k = idx - c * 96;
        g_decP[idx] = decW[k * NACT + c];
    }
}

// ---------------- helpers ----------------
__device__ __forceinline__ void ffma2(ull& acc, ull a, ull b) {
    asm("fma.rn.f32x2 %0, %1, %2, %0;" : "+l"(acc) : "l"(a), "l"(b));
}
__device__ __forceinline__ ull pack2(float x) {
    ull d; unsigned xi = __float_as_uint(x);
    asm("mov.b64 %0, {%1, %1};" : "=l"(d) : "r"(xi));
    return d;
}
__device__ __forceinline__ ull pack_ab(float a, float b) {
    ull d;
    asm("mov.b64 %0, {%1, %2};" : "=l"(d) : "f"(a), "f"(b));
    return d;
}
__device__ __forceinline__ float2 unpack2(ull v) {
    float2 r;
    asm("mov.b64 {%0, %1}, %2;" : "=f"(r.x), "=f"(r.y) : "l"(v));
    return r;
}
__device__ __forceinline__ float hsum2(ull v) { float2 r = unpack2(v); return r.x + r.y; }
__device__ __forceinline__ unsigned saddr(const void* p) {
    return (unsigned)__cvta_generic_to_shared(p);
}
__device__ __forceinline__ float tanh_fast(float x) {
    float r; asm("tanh.approx.f32 %0, %1;" : "=f"(r) : "f"(x)); return r;
}
__device__ __forceinline__ float sigmoid_fast(float s) {
    return fmaf(tanh_fast(0.5f * s), 0.5f, 0.5f);
}
__device__ __forceinline__ float2 ldg64_nc(const float* p) {
    float2 v;
    asm("ld.global.nc.v2.f32 {%0,%1}, [%2];"
        : "=f"(v.x), "=f"(v.y) : "l"(p));
    return v;
}
__device__ __forceinline__ void mma_tf32(float* d,
                                         unsigned a0, unsigned a1, unsigned a2, unsigned a3,
                                         unsigned b0, unsigned b1) {
    asm("mma.sync.aligned.m16n8k8.row.col.f32.tf32.tf32.f32 "
        "{%0,%1,%2,%3}, {%4,%5,%6,%7}, {%8,%9}, {%0,%1,%2,%3};"
        : "+f"(d[0]), "+f"(d[1]), "+f"(d[2]), "+f"(d[3])
        : "r"(a0), "r"(a1), "r"(a2), "r"(a3), "r"(b0), "r"(b1));
}
__device__ __forceinline__ void ldsm_x4(unsigned& a0, unsigned& a1, unsigned& a2, unsigned& a3,
                                        unsigned addr) {
    asm volatile("ldmatrix.sync.aligned.m8n8.x4.shared.b16 {%0,%1,%2,%3}, [%4];"
        : "=r"(a0), "=r"(a1), "=r"(a2), "=r"(a3) : "r"(addr));
}

// single n-tile, 4 m-tile, 8 ks (frag LDGs hoisted)
__device__ __forceinline__ void mma_pass1(const float* __restrict__ src, int pitch,
                                          const float* __restrict__ frag,
                                          int fksBase, int ntStride, int fnt,
                                          int lane, float* acc)
{
    const int rsel = lane & 15;
    const int csel = (lane & 16) ? 4 : 0;
    float2 fr[8];
#pragma unroll
    for (int ks = 0; ks < 8; ks++)
        fr[ks] = ldg64_nc(&frag[(((fksBase + ks) * ntStride + fnt) * 32 + lane) * 2]);
#pragma unroll
    for (int ks = 0; ks < 8; ks++) {
        const int kcol = ks * 8 + csel;
        const unsigned b0 = __float_as_uint(fr[ks].x), b1 = __float_as_uint(fr[ks].y);
#pragma unroll
        for (int mt = 0; mt < 4; mt++) {
            unsigned a0, a1, a2, a3;
            ldsm_x4(a0, a1, a2, a3, saddr(&src[(mt * 16 + rsel) * pitch + kcol]));
            mma_tf32(acc + mt * 4, a0, a1, a2, a3, b0, b1);
        }
    }
}

// DUAL n-tile pass: A-fragments loaded once, feed two accumulator sets
__device__ __forceinline__ void mma_passD(const float* __restrict__ src, int pitch,
                                          const float* __restrict__ frag,
                                          int fksBase, int ntStride, int fnt0, int fnt1,
                                          int lane, float* accA, float* accB)
{
    const int rsel = lane & 15;
    const int csel = (lane & 16) ? 4 : 0;
#pragma unroll
    for (int kc = 0; kc < 8; kc += 4) {
        float2 frA[4], frB[4];
#pragma unroll
        for (int ks = 0; ks < 4; ks++) {
            frA[ks] = ldg64_nc(&frag[(((fksBase + kc + ks) * ntStride + fnt0) * 32 + lane) * 2]);
            frB[ks] = ldg64_nc(&frag[(((fksBase + kc + ks) * ntStride + fnt1) * 32 + lane) * 2]);
        }
#pragma unroll
        for (int ks = 0; ks < 4; ks++) {
            const int kcol = (kc + ks) * 8 + csel;
#pragma unroll
            for (int mt = 0; mt < 4; mt++) {
                unsigned a0, a1, a2, a3;
                ldsm_x4(a0, a1, a2, a3, saddr(&src[(mt * 16 + rsel) * pitch + kcol]));
                mma_tf32(accA + mt * 4, a0, a1, a2, a3,
                         __float_as_uint(frA[ks].x), __float_as_uint(frA[ks].y));
                mma_tf32(accB + mt * 4, a0, a1, a2, a3,
                         __float_as_uint(frB[ks].x), __float_as_uint(frB[ks].y));
            }
        }
    }
}

__global__ void __launch_bounds__(NTHREADS, 3)
fused_kernel(const float* __restrict__ obs,
             const float* __restrict__ hid,
             const float* __restrict__ encb,
             const float* __restrict__ bih,
             const float* __restrict__ bhh,
             const float* __restrict__ vb,
             const float* __restrict__ decb,
             float* __restrict__ outp,
             float* __restrict__ houtp)
{
    extern __shared__ float sm[];
    // regionA [0, 8704): obs double buffer -> later ho_r (64 x PHO = 6400)
    float* Abuf0 = sm;
    float* Abuf1 = sm + 4352;
    float* ho_r  = sm;                 // [64 rows][PHO]
    // regionB [8704, 17408): x_r + h_r -> later qkv_s (96 x PT = 6528) + out_s (896)
    float* x_r   = sm + 8704;          // [64 rows][PO]
    float* h_r   = sm + 13056;         // [64 rows][PO]
    float* qkv_s = sm + 8704;          // [96 feat][PT]
    float* out_s = sm + 8704 + 6528;   // [64 rows][14]

    const int tid  = threadIdx.x;
    const int w    = tid >> 5;
    const int lane = tid & 31;
    const int g    = lane >> 2;
    const int tg   = lane & 3;
    const int rowbase = blockIdx.x * BM;

    // ---- prefetch obs tile 0 via cp.async ----
    {
#pragma unroll
        for (int c = 0; c < 4; c++) {
            int chunk = tid + c * 256;
            int row = chunk >> 4, off = (chunk & 15) * 4;
            const float* src = obs + (size_t)(rowbase + row) * DIN + off;
            unsigned d = saddr(&Abuf0[row * PO + off]);
            asm volatile("cp.async.cg.shared.global [%0], [%1], 16;" :: "r"(d), "l"(src));
        }
        asm volatile("cp.async.commit_group;");
    }

    // ---- load hidden_state row-major ----
    for (int v = tid; v < BM * 16; v += NTHREADS) {
        int r = v >> 4, c4 = (v & 15) * 4;
        *reinterpret_cast<float4*>(&h_r[r * PO + c4]) =
            *reinterpret_cast<const float4*>(&hid[(size_t)(rowbase + r) * HDIM + c4]);
    }

    // ---------------- encoder via tf32 mma: warp w owns n-tile w, 64 rows ----
    {
        float d[16];
#pragma unroll
        for (int e = 0; e < 16; e++) d[e] = 0.f;

#pragma unroll
        for (int kt = 0; kt < 4; kt++) {
            __syncthreads();
            if (kt < 3) {
                float* dst = ((kt + 1) & 1) ? Abuf1 : Abuf0;
#pragma unroll
                for (int c = 0; c < 4; c++) {
                    int chunk = tid + c * 256;
                    int row = chunk >> 4, off = (chunk & 15) * 4;
                    const float* src = obs + (size_t)(rowbase + row) * DIN + (kt + 1) * 64 + off;
                    unsigned dsta = saddr(&dst[row * PO + off]);
                    asm volatile("cp.async.cg.shared.global [%0], [%1], 16;" :: "r"(dsta), "l"(src));
                }
                asm volatile("cp.async.commit_group;");
                asm volatile("cp.async.wait_group 1;");
            } else {
                asm volatile("cp.async.wait_group 0;");
            }
            __syncthreads();

            const float* Ac = (kt & 1) ? Abuf1 : Abuf0;
            mma_pass1(Ac, PO, g_encF, kt * 8, 8, w, lane, d);
        }

        const int col0 = w * 8 + tg * 2;
        const float b0 = encb[col0], b1 = encb[col0 + 1];
#pragma unroll
        for (int mt = 0; mt < 4; mt++) {
            const int row0 = mt * 16 + g;
            const float* am = d + mt * 4;
            *reinterpret_cast<ull*>(&x_r[row0 * PO + col0]) =
                pack_ab(fmaxf(am[0] + b0, 0.f), fmaxf(am[1] + b1, 0.f));
            *reinterpret_cast<ull*>(&x_r[(row0 + 8) * PO + col0]) =
                pack_ab(fmaxf(am[2] + b0, 0.f), fmaxf(am[3] + b1, 0.f));
        }
    }
    __syncthreads();

    // ---------------- GRU via tf32 mma, dual-acc r/z sweeps ----------------
    {
        const int col0 = w * 8 + tg * 2;
        float accR[16], accZ[16];
#pragma unroll
        for (int e = 0; e < 16; e++) { accR[e] = 0.f; accZ[e] = 0.f; }

        mma_passD(x_r, PO, g_gruF, 0, 24, w, 8 + w, lane, accR, accZ);
        mma_passD(h_r, PO, g_gruF, 8, 24, w, 8 + w, lane, accR, accZ);

        // r = sigmoid(accR + biases)
        {
            const float2 b1 = *reinterpret_cast<const float2*>(&bih[col0]);
            const float2 b2 = *reinterpret_cast<const float2*>(&bhh[col0]);
            const float bx = b1.x + b2.x, by = b1.y + b2.y;
#pragma unroll
            for (int mt = 0; mt < 4; mt++) {
                float* a = accR + mt * 4;
                a[0] = sigmoid_fast(a[0] + bx);
                a[1] = sigmoid_fast(a[1] + by);
                a[2] = sigmoid_fast(a[2] + bx);
                a[3] = sigmoid_fast(a[3] + by);
            }
        }
        // hn: accR = r * (h@Un + bhh_n)
        {
            float accN[16];
#pragma unroll
            for (int e = 0; e < 16; e++) accN[e] = 0.f;
            mma_pass1(h_r, PO, g_gruF, 8, 24, 16 + w, lane, accN);
            const float2 b2 = *reinterpret_cast<const float2*>(&bhh[128 + col0]);
#pragma unroll
            for (int mt = 0; mt < 4; mt++) {
                float* a = accN + mt * 4;
                float* c = accR + mt * 4;
                c[0] *= (a[0] + b2.x); c[1] *= (a[1] + b2.y);
                c[2] *= (a[2] + b2.x); c[3] *= (a[3] + b2.y);
            }
        }
        // xn: accR = tanh(x@Wn + bih_n + accR)
        {
            float accN[16];
#pragma unroll
            for (int e = 0; e < 16; e++) accN[e] = 0.f;
            mma_pass1(x_r, PO, g_gruF, 0, 24, 16 + w, lane, accN);
            const float2 b1 = *reinterpret_cast<const float2*>(&bih[128 + col0]);
#pragma unroll
            for (int mt = 0; mt < 4; mt++) {
                float* a = accN + mt * 4;
                float* c = accR + mt * 4;
                c[0] = tanh_fast(a[0] + b1.x + c[0]);
                c[1] = tanh_fast(a[1] + b1.y + c[1]);
                c[2] = tanh_fast(a[2] + b1.x + c[2]);
                c[3] = tanh_fast(a[3] + b1.y + c[3]);
            }
        }
        // z (from accZ) + blend + store ho_r
        {
            const float2 b1 = *reinterpret_cast<const float2*>(&bih[64 + col0]);
            const float2 b2 = *reinterpret_cast<const float2*>(&bhh[64 + col0]);
            const float bx = b1.x + b2.x, by = b1.y + b2.y;
#pragma unroll
            for (int mt = 0; mt < 4; mt++) {
                float* a = accZ + mt * 4;
                float* n = accR + mt * 4;
                const int rA = mt * 16 + g, rB = rA + 8;
                float z0 = sigmoid_fast(a[0] + bx);
                float z1 = sigmoid_fast(a[1] + by);
                float z2 = sigmoid_fast(a[2] + bx);
                float z3 = sigmoid_fast(a[3] + by);
                const float2 hA = *reinterpret_cast<const float2*>(&h_r[rA * PO + col0]);
                const float2 hB = *reinterpret_cast<const float2*>(&h_r[rB * PO + col0]);
                *reinterpret_cast<ull*>(&ho_r[rA * PHO + col0]) =
                    pack_ab((1.f - z0) * n[0] + z0 * hA.x, (1.f - z1) * n[1] + z1 * hA.y);
                *reinterpret_cast<ull*>(&ho_r[rB * PHO + col0]) =
                    pack_ab((1.f - z2) * n[2] + z2 * hB.x, (1.f - z3) * n[3] + z3 * hB.y);
            }
        }
    }
    __syncthreads();

    // ---------------- h_out writeback + QKV via tf32 mma --------------------
    {
        for (int v = tid; v < BM * 16; v += NTHREADS) {
            int r = v >> 4, c4 = (v & 15) * 4;
            *reinterpret_cast<float4*>(&houtp[(size_t)(rowbase + r) * HDIM + c4]) =
                *reinterpret_cast<const float4*>(&ho_r[r * PHO + c4]);
        }

        float acc1[16], acc2[16];
#pragma unroll
        for (int e = 0; e < 16; e++) { acc1[e] = 0.f; acc2[e] = 0.f; }
        if (w < 4) {
            mma_passD(ho_r, PHO, g_qkvF, 0, 12, w, 8 + w, lane, acc1, acc2);
        } else {
            mma_pass1(ho_r, PHO, g_qkvF, 0, 12, w, lane, acc1);
        }

        __syncthreads();   // x_r/h_r fully dead before qkv_s overlay writes

        {
            const int col0 = w * 8 + tg * 2;   // 0..63 (q|k): no bias/relu
#pragma unroll
            for (int mt = 0; mt < 4; mt++) {
                const int rA = mt * 16 + g, rB = rA + 8;
                float* a = acc1 + mt * 4;
                qkv_s[col0 * PT + rA]       = a[0];
                qkv_s[(col0 + 1) * PT + rA] = a[1];
                qkv_s[col0 * PT + rB]       = a[2];
                qkv_s[(col0 + 1) * PT + rB] = a[3];
            }
        }
        if (w < 4) {
            const int col0 = 64 + w * 8 + tg * 2;   // v cols: bias + relu
            const float b0 = vb[col0 - 64], b1 = vb[col0 - 63];
#pragma unroll
            for (int mt = 0; mt < 4; mt++) {
                const int rA = mt * 16 + g, rB = rA + 8;
                float* a = acc2 + mt * 4;
                qkv_s[col0 * PT + rA]       = fmaxf(a[0] + b0, 0.f);
                qkv_s[(col0 + 1) * PT + rA] = fmaxf(a[1] + b1, 0.f);
                qkv_s[col0 * PT + rB]       = fmaxf(a[2] + b0, 0.f);
                qkv_s[(col0 + 1) * PT + rB] = fmaxf(a[3] + b1, 0.f);
            }
        }
    }
    __syncthreads();

    // ---------------- attention (tid<64)  ||  decoder h_out-part (tid>=64) --
    if (tid < BM) {
        const int ii = tid & 7;
        const int base = tid & ~7;
        ull sp[4] = {0, 0, 0, 0};
#pragma unroll 8
        for (int a = 0; a < ADIM; a++) {
            ull qa = pack2(qkv_s[a * PT + tid]);
            const ulonglong2 k01 = *reinterpret_cast<const ulonglong2*>(&qkv_s[(32 + a) * PT + base]);
            const ulonglong2 k23 = *reinterpret_cast<const ulonglong2*>(&qkv_s[(32 + a) * PT + base + 4]);
            ffma2(sp[0], k01.x, qa); ffma2(sp[1], k01.y, qa);
            ffma2(sp[2], k23.x, qa); ffma2(sp[3], k23.y, qa);
        }
        float sc[NS];
#pragma unroll
        for (int jp = 0; jp < 4; jp++) {
            float2 v = unpack2(sp[jp]);
            sc[2 * jp]     = v.x * 0.17677669529663689f;
            sc[2 * jp + 1] = v.y * 0.17677669529663689f;
        }
        sc[ii] = -1e9f;
        float mx = -1e30f;
#pragma unroll
        for (int j = 0; j < NS; j++) mx = fmaxf(mx, sc[j]);
        float sum = 0.f;
#pragma unroll
        for (int j = 0; j < NS; j++) { sc[j] = __expf(sc[j] - mx); sum += sc[j]; }
        const float inv = __fdividef(1.f, sum);
        ull wp[4];
#pragma unroll
        for (int jp = 0; jp < 4; jp++)
            wp[jp] = pack_ab(sc[2 * jp] * inv, sc[2 * jp + 1] * inv);
        float xa[ADIM];
#pragma unroll 8
        for (int a = 0; a < ADIM; a++) {
            const ulonglong2 v01 = *reinterpret_cast<const ulonglong2*>(&qkv_s[(64 + a) * PT + base]);
            const ulonglong2 v23 = *reinterpret_cast<const ulonglong2*>(&qkv_s[(64 + a) * PT + base + 4]);
            ull t = 0;
            ffma2(t, v01.x, wp[0]); ffma2(t, v01.y, wp[1]);
            ffma2(t, v23.x, wp[2]); ffma2(t, v23.y, wp[3]);
            xa[a] = hsum2(t);
        }
#pragma unroll
        for (int a4 = 0; a4 < 8; a4++) {
            float4 o = make_float4(xa[a4 * 4], xa[a4 * 4 + 1], xa[a4 * 4 + 2], xa[a4 * 4 + 3]);
            *reinterpret_cast<float4*>(&ho_r[tid * PHO + 64 + a4 * 4]) = o;
        }
    } else {
        // decoder partial: h_out part (k 0..63) + bias -> out_s
        for (int it = tid - BM; it < 448; it += NTHREADS - BM) {
            int pr = it & 31, c = it >> 5;
            const float* hA = &ho_r[(2 * pr) * PHO];
            const float* hB = &ho_r[(2 * pr + 1) * PHO];
            ull acc0 = 0, acc1 = 0;
#pragma unroll 8
            for (int k4 = 0; k4 < 16; k4++) {
                const ulonglong2 wv = *reinterpret_cast<const ulonglong2*>(&g_decP[c * 96 + k4 * 4]);
                const ulonglong2 a4 = *reinterpret_cast<const ulonglong2*>(&hA[k4 * 4]);
                const ulonglong2 b4 = *reinterpret_cast<const ulonglong2*>(&hB[k4 * 4]);
                ffma2(acc0, a4.x, wv.x); ffma2(acc0, a4.y, wv.y);
                ffma2(acc1, b4.x, wv.x); ffma2(acc1, b4.y, wv.y);
            }
            float b = decb[c];
            out_s[(2 * pr) * NACT + c]     = hsum2(acc0) + b;
            out_s[(2 * pr + 1) * NACT + c] = hsum2(acc1) + b;
        }
    }
    __syncthreads();

    // ---------------- decoder xatt part (all threads) + coalesced store -----
    for (int it = tid; it < 448; it += NTHREADS) {
        int pr = it & 31, c = it >> 5;
        const float* xA = &ho_r[(2 * pr) * PHO + 64];
        const float* xB = &ho_r[(2 * pr + 1) * PHO + 64];
        ull acc0 = 0, acc1 = 0;
#pragma unroll 8
        for (int k4 = 0; k4 < 8; k4++) {
            const ulonglong2 wv = *reinterpret_cast<const ulonglong2*>(&g_decP[c * 96 + 64 + k4 * 4]);
            const ulonglong2 a4 = *reinterpret_cast<const ulonglong2*>(&xA[k4 * 4]);
            const ulonglong2 b4 = *reinterpret_cast<const ulonglong2*>(&xB[k4 * 4]);
            ffma2(acc0, a4.x, wv.x); ffma2(acc0, a4.y, wv.y);
            ffma2(acc1, b4.x, wv.x); ffma2(acc1, b4.y, wv.y);
        }
        out_s[(2 * pr) * NACT + c]     += hsum2(acc0);
        out_s[(2 * pr + 1) * NACT + c] += hsum2(acc1);
    }
    __syncthreads();
    {
        float4* dst = reinterpret_cast<float4*>(outp + (size_t)rowbase * NACT);
        const float4* src = reinterpret_cast<const float4*>(out_s);
        for (int v = tid; v < (BM * NACT) / 4; v += NTHREADS)
            dst[v] = src[v];
    }
}

extern "C" void kernel_launch(void* const* d_in, const int* in_sizes, int n_in,
                              void* d_out, int out_size)
{
    (void)in_sizes; (void)n_in; (void)out_size;
    const float* obs  = (const float*)d_in[0];
    const float* hid  = (const float*)d_in[1];
    const float* encW = (const float*)d_in[2];
    const float* encb = (const float*)d_in[3];
    const float* Wih  = (const float*)d_in[4];
    const float* Whh  = (const float*)d_in[5];
    const float* bih  = (const float*)d_in[6];
    const float* bhh  = (const float*)d_in[7];
    const float* qW   = (const float*)d_in[8];
    const float* kW   = (const float*)d_in[9];
    const float* vW   = (const float*)d_in[10];
    const float* vb   = (const float*)d_in[11];
    const float* decW = (const float*)d_in[12];
    const float* decb = (const float*)d_in[13];

    float* outp  = (float*)d_out;                 // [B, 14]
    float* houtp = outp + (size_t)BTOT * NACT;    // [B, 64]

    setup_kernel<<<64, 256>>>(encW, Wih, Whh, qW, kW, vW, decW);

    const int smem_bytes = 17408 * sizeof(float); // 69,632 B -> 3 CTAs/SM
    cudaFuncSetAttribute(fused_kernel,
                         cudaFuncAttributeMaxDynamicSharedMemorySize, smem_bytes);
    fused_kernel<<<BTOT / BM, NTHREADS, smem_bytes>>>(
        obs, hid, encb, bih, bhh, vb, decb, outp, houtp);
}

// round 17
// speedup vs baseline: 1.2928x; 1.0307x over previous
#include <cuda_runtime.h>
#include <math.h>

#define BTOT   65536
#define DIN    256
#define HDIM   64
#define ADIM   32
#define NACT   14
#define NS     8
#define BM     64
#define PO     68        // row-major pitch (Abuf, x_r, h_r)
#define PT     68        // feature-major pitch (qkv_s)
#define PHO    100       // ho_r row pitch
#define NTHREADS 256

typedef unsigned long long ull;

// ---- persistent fragment-packed tf32 weights + decoder weights ----
__device__ __align__(16) float g_encF[32 * 8 * 64];    // [ks][nt][lane][2]
__device__ __align__(16) float g_gruF[16 * 24 * 64];   // [ks][nt][lane][2]
__device__ __align__(16) float g_qkvF[8 * 12 * 64];    // [ks][nt][lane][2]
__device__ __align__(16) float g_decP[NACT * 96];      // [c][k]

__device__ __forceinline__ unsigned to_tf32(float x) {
    unsigned r; asm("cvt.rna.tf32.f32 %0, %1;" : "=r"(r) : "f"(x)); return r;
}

__global__ void setup_kernel(const float* __restrict__ encW,
                             const float* __restrict__ Wih,
                             const float* __restrict__ Whh,
                             const float* __restrict__ qW,
                             const float* __restrict__ kW,
                             const float* __restrict__ vW,
                             const float* __restrict__ decW)
{
    const int stride = gridDim.x * blockDim.x;
    const int t0 = blockIdx.x * blockDim.x + threadIdx.x;

    for (int idx = t0; idx < 32 * 8 * 64; idx += stride) {
        int p = idx & 1, lane = (idx >> 1) & 31;
        int rest = idx >> 6;
        int nt = rest & 7, ks = rest >> 3;
        int krow = ks * 8 + (lane & 3) + 4 * p;
        int col  = nt * 8 + (lane >> 2);
        g_encF[idx] = __uint_as_float(to_tf32(encW[krow * HDIM + col]));
    }
    for (int idx = t0; idx < 16 * 24 * 64; idx += stride) {
        int p = idx & 1, lane = (idx >> 1) & 31;
        int rest = idx >> 6;
        int nt = rest % 24, ks = rest / 24;
        int krow = ks * 8 + (lane & 3) + 4 * p;   // 0..127
        int col  = nt * 8 + (lane >> 2);          // 0..191
        float v = (krow < 64) ? Wih[col * HDIM + krow] : Whh[col * HDIM + (krow - 64)];
        g_gruF[idx] = __uint_as_float(to_tf32(v));
    }
    for (int idx = t0; idx < 8 * 12 * 64; idx += stride) {
        int p = idx & 1, lane = (idx >> 1) & 31;
        int rest = idx >> 6;
        int nt = rest % 12, ks = rest / 12;
        int krow = ks * 8 + (lane & 3) + 4 * p;   // 0..63
        int col  = nt * 8 + (lane >> 2);          // 0..95
        float v;
        if (col < 32)      v = qW[krow * 32 + col];
        else if (col < 64) v = kW[krow * 32 + (col - 32)];
        else               v = vW[krow * 32 + (col - 64)];
        g_qkvF[idx] = __uint_as_float(to_tf32(v));
    }
    for (int idx = t0; idx < NACT * 96; idx += stride) {
        int c = idx / 96, k = idx - c * 96;
        g_decP[idx] = decW[k * NACT + c];
    }
}

// ---------------- helpers ----------------
__device__ __forceinline__ void ffma2(ull& acc, ull a, ull b) {
    asm("fma.rn.f32x2 %0, %1, %2, %0;" : "+l"(acc) : "l"(a), "l"(b));
}
__device__ __forceinline__ ull pack2(float x) {
    ull d; unsigned xi = __float_as_uint(x);
    asm("mov.b64 %0, {%1, %1};" : "=l"(d) : "r"(xi));
    return d;
}
__device__ __forceinline__ ull pack_ab(float a, float b) {
    ull d;
    asm("mov.b64 %0, {%1, %2};" : "=l"(d) : "f"(a), "f"(b));
    return d;
}
__device__ __forceinline__ float2 unpack2(ull v) {
    float2 r;
    asm("mov.b64 {%0, %1}, %2;" : "=f"(r.x), "=f"(r.y) : "l"(v));
    return r;
}
__device__ __forceinline__ float hsum2(ull v) { float2 r = unpack2(v); return r.x + r.y; }
__device__ __forceinline__ unsigned saddr(const void* p) {
    return (unsigned)__cvta_generic_to_shared(p);
}
__device__ __forceinline__ float tanh_fast(float x) {
    float r; asm("tanh.approx.f32 %0, %1;" : "=f"(r) : "f"(x)); return r;
}
__device__ __forceinline__ float sigmoid_fast(float s) {
    return fmaf(tanh_fast(0.5f * s), 0.5f, 0.5f);
}
__device__ __forceinline__ float2 ldg64_nc(const float* p) {
    float2 v;
    asm("ld.global.nc.v2.f32 {%0,%1}, [%2];"
        : "=f"(v.x), "=f"(v.y) : "l"(p));
    return v;
}
__device__ __forceinline__ ull mk_evict_first_policy() {
    ull pol;
    asm("createpolicy.fractional.L2::evict_first.b64 %0, 1.0;" : "=l"(pol));
    return pol;
}
__device__ __forceinline__ void cp_async16_ef(unsigned d, const float* s, ull pol) {
    asm volatile("cp.async.cg.shared.global.L2::cache_hint [%0], [%1], 16, %2;"
                 :: "r"(d), "l"(s), "l"(pol));
}
__device__ __forceinline__ void mma_tf32(float* d,
                                         unsigned a0, unsigned a1, unsigned a2, unsigned a3,
                                         unsigned b0, unsigned b1) {
    asm("mma.sync.aligned.m16n8k8.row.col.f32.tf32.tf32.f32 "
        "{%0,%1,%2,%3}, {%4,%5,%6,%7}, {%8,%9}, {%0,%1,%2,%3};"
        : "+f"(d[0]), "+f"(d[1]), "+f"(d[2]), "+f"(d[3])
        : "r"(a0), "r"(a1), "r"(a2), "r"(a3), "r"(b0), "r"(b1));
}
__device__ __forceinline__ void ldsm_x4(unsigned& a0, unsigned& a1, unsigned& a2, unsigned& a3,
                                        unsigned addr) {
    asm volatile("ldmatrix.sync.aligned.m8n8.x4.shared.b16 {%0,%1,%2,%3}, [%4];"
        : "=r"(a0), "=r"(a1), "=r"(a2), "=r"(a3) : "r"(addr));
}

// single n-tile, 4 m-tile, 8 ks (frag LDGs hoisted)
__device__ __forceinline__ void mma_pass1(const float* __restrict__ src, int pitch,
                                          const float* __restrict__ frag,
                                          int fksBase, int ntStride, int fnt,
                                          int lane, float* acc)
{
    const int rsel = lane & 15;
    const int csel = (lane & 16) ? 4 : 0;
    float2 fr[8];
#pragma unroll
    for (int ks = 0; ks < 8; ks++)
        fr[ks] = ldg64_nc(&frag[(((fksBase + ks) * ntStride + fnt) * 32 + lane) * 2]);
#pragma unroll
    for (int ks = 0; ks < 8; ks++) {
        const int kcol = ks * 8 + csel;
        const unsigned b0 = __float_as_uint(fr[ks].x), b1 = __float_as_uint(fr[ks].y);
#pragma unroll
        for (int mt = 0; mt < 4; mt++) {
            unsigned a0, a1, a2, a3;
            ldsm_x4(a0, a1, a2, a3, saddr(&src[(mt * 16 + rsel) * pitch + kcol]));
            mma_tf32(acc + mt * 4, a0, a1, a2, a3, b0, b1);
        }
    }
}

// DUAL n-tile pass: A-fragments loaded once, feed two accumulator sets
__device__ __forceinline__ void mma_passD(const float* __restrict__ src, int pitch,
                                          const float* __restrict__ frag,
                                          int fksBase, int ntStride, int fnt0, int fnt1,
                                          int lane, float* accA, float* accB)
{
    const int rsel = lane & 15;
    const int csel = (lane & 16) ? 4 : 0;
#pragma unroll
    for (int kc = 0; kc < 8; kc += 4) {
        float2 frA[4], frB[4];
#pragma unroll
        for (int ks = 0; ks < 4; ks++) {
            frA[ks] = ldg64_nc(&frag[(((fksBase + kc + ks) * ntStride + fnt0) * 32 + lane) * 2]);
            frB[ks] = ldg64_nc(&frag[(((fksBase + kc + ks) * ntStride + fnt1) * 32 + lane) * 2]);
        }
#pragma unroll
        for (int ks = 0; ks < 4; ks++) {
            const int kcol = (kc + ks) * 8 + csel;
#pragma unroll
            for (int mt = 0; mt < 4; mt++) {
                unsigned a0, a1, a2, a3;
                ldsm_x4(a0, a1, a2, a3, saddr(&src[(mt * 16 + rsel) * pitch + kcol]));
                mma_tf32(accA + mt * 4, a0, a1, a2, a3,
                         __float_as_uint(frA[ks].x), __float_as_uint(frA[ks].y));
                mma_tf32(accB + mt * 4, a0, a1, a2, a3,
                         __float_as_uint(frB[ks].x), __float_as_uint(frB[ks].y));
            }
        }
    }
}

__global__ void __launch_bounds__(NTHREADS, 3)
fused_kernel(const float* __restrict__ obs,
             const float* __restrict__ hid,
             const float* __restrict__ encb,
             const float* __restrict__ bih,
             const float* __restrict__ bhh,
             const float* __restrict__ vb,
             const float* __restrict__ decb,
             float* __restrict__ outp,
             float* __restrict__ houtp)
{
    extern __shared__ float sm[];
    // regionA [0, 8704): obs double buffer -> later ho_r (64 x PHO = 6400)
    float* Abuf0 = sm;
    float* Abuf1 = sm + 4352;
    float* ho_r  = sm;                 // [64 rows][PHO]
    // regionB [8704, 17408): x_r + h_r -> later qkv_s (96 x PT = 6528) + out_s (896)
    float* x_r   = sm + 8704;          // [64 rows][PO]
    float* h_r   = sm + 13056;         // [64 rows][PO]
    float* qkv_s = sm + 8704;          // [96 feat][PT]
    float* out_s = sm + 8704 + 6528;   // [64 rows][14]

    const int tid  = threadIdx.x;
    const int w    = tid >> 5;
    const int lane = tid & 31;
    const int g    = lane >> 2;
    const int tg   = lane & 3;
    const int rowbase = blockIdx.x * BM;
    const ull pol = mk_evict_first_policy();

    // ---- prefetch obs tile 0 via cp.async (L2 evict_first) ----
    {
#pragma unroll
        for (int c = 0; c < 4; c++) {
            int chunk = tid + c * 256;
            int row = chunk >> 4, off = (chunk & 15) * 4;
            const float* src = obs + (size_t)(rowbase + row) * DIN + off;
            cp_async16_ef(saddr(&Abuf0[row * PO + off]), src, pol);
        }
        asm volatile("cp.async.commit_group;");
    }

    // ---- load hidden_state row-major (streaming) ----
    for (int v = tid; v < BM * 16; v += NTHREADS) {
        int r = v >> 4, c4 = (v & 15) * 4;
        *reinterpret_cast<float4*>(&h_r[r * PO + c4]) =
            __ldcs(reinterpret_cast<const float4*>(&hid[(size_t)(rowbase + r) * HDIM + c4]));
    }

    // ---------------- encoder via tf32 mma: warp w owns n-tile w, 64 rows ----
    {
        float d[16];
#pragma unroll
        for (int e = 0; e < 16; e++) d[e] = 0.f;

#pragma unroll
        for (int kt = 0; kt < 4; kt++) {
            __syncthreads();
            if (kt < 3) {
                float* dst = ((kt + 1) & 1) ? Abuf1 : Abuf0;
#pragma unroll
                for (int c = 0; c < 4; c++) {
                    int chunk = tid + c * 256;
                    int row = chunk >> 4, off = (chunk & 15) * 4;
                    const float* src = obs + (size_t)(rowbase + row) * DIN + (kt + 1) * 64 + off;
                    cp_async16_ef(saddr(&dst[row * PO + off]), src, pol);
                }
                asm volatile("cp.async.commit_group;");
                asm volatile("cp.async.wait_group 1;");
            } else {
                asm volatile("cp.async.wait_group 0;");
            }
            __syncthreads();

            const float* Ac = (kt & 1) ? Abuf1 : Abuf0;
            mma_pass1(Ac, PO, g_encF, kt * 8, 8, w, lane, d);
        }

        const int col0 = w * 8 + tg * 2;
        const float b0 = encb[col0], b1 = encb[col0 + 1];
#pragma unroll
        for (int mt = 0; mt < 4; mt++) {
            const int row0 = mt * 16 + g;
            const float* am = d + mt * 4;
            *reinterpret_cast<ull*>(&x_r[row0 * PO + col0]) =
                pack_ab(fmaxf(am[0] + b0, 0.f), fmaxf(am[1] + b1, 0.f));
            *reinterpret_cast<ull*>(&x_r[(row0 + 8) * PO + col0]) =
                pack_ab(fmaxf(am[2] + b0, 0.f), fmaxf(am[3] + b1, 0.f));
        }
    }
    __syncthreads();

    // ---------------- GRU via tf32 mma, dual-acc r/z sweeps ----------------
    {
        const int col0 = w * 8 + tg * 2;
        float accR[16], accZ[16];
#pragma unroll
        for (int e = 0; e < 16; e++) { accR[e] = 0.f; accZ[e] = 0.f; }

        mma_passD(x_r, PO, g_gruF, 0, 24, w, 8 + w, lane, accR, accZ);
        mma_passD(h_r, PO, g_gruF, 8, 24, w, 8 + w, lane, accR, accZ);

        // r = sigmoid(accR + biases)
        {
            const float2 b1 = *reinterpret_cast<const float2*>(&bih[col0]);
            const float2 b2 = *reinterpret_cast<const float2*>(&bhh[col0]);
            const float bx = b1.x + b2.x, by = b1.y + b2.y;
#pragma unroll
            for (int mt = 0; mt < 4; mt++) {
                float* a = accR + mt * 4;
                a[0] = sigmoid_fast(a[0] + bx);
                a[1] = sigmoid_fast(a[1] + by);
                a[2] = sigmoid_fast(a[2] + bx);
                a[3] = sigmoid_fast(a[3] + by);
            }
        }
        // hn: accR = r * (h@Un + bhh_n)
        {
            float accN[16];
#pragma unroll
            for (int e = 0; e < 16; e++) accN[e] = 0.f;
            mma_pass1(h_r, PO, g_gruF, 8, 24, 16 + w, lane, accN);
            const float2 b2 = *reinterpret_cast<const float2*>(&bhh[128 + col0]);
#pragma unroll
            for (int mt = 0; mt < 4; mt++) {
                float* a = accN + mt * 4;
                float* c = accR + mt * 4;
                c[0] *= (a[0] + b2.x); c[1] *= (a[1] + b2.y);
                c[2] *= (a[2] + b2.x); c[3] *= (a[3] + b2.y);
            }
        }
        // xn: accR = tanh(x@Wn + bih_n + accR)
        {
            float accN[16];
#pragma unroll
            for (int e = 0; e < 16; e++) accN[e] = 0.f;
            mma_pass1(x_r, PO, g_gruF, 0, 24, 16 + w, lane, accN);
            const float2 b1 = *reinterpret_cast<const float2*>(&bih[128 + col0]);
#pragma unroll
            for (int mt = 0; mt < 4; mt++) {
                float* a = accN + mt * 4;
                float* c = accR + mt * 4;
                c[0] = tanh_fast(a[0] + b1.x + c[0]);
                c[1] = tanh_fast(a[1] + b1.y + c[1]);
                c[2] = tanh_fast(a[2] + b1.x + c[2]);
                c[3] = tanh_fast(a[3] + b1.y + c[3]);
            }
        }
        // z (from accZ) + blend + store ho_r
        {
            const float2 b1 = *reinterpret_cast<const float2*>(&bih[64 + col0]);
            const float2 b2 = *reinterpret_cast<const float2*>(&bhh[64 + col0]);
            const float bx = b1.x + b2.x, by = b1.y + b2.y;
#pragma unroll
            for (int mt = 0; mt < 4; mt++) {
                float* a = accZ + mt * 4;
                float* n = accR + mt * 4;
                const int rA = mt * 16 + g, rB = rA + 8;
                float z0 = sigmoid_fast(a[0] + bx);
                float z1 = sigmoid_fast(a[1] + by);
                float z2 = sigmoid_fast(a[2] + bx);
                float z3 = sigmoid_fast(a[3] + by);
                const float2 hA = *reinterpret_cast<const float2*>(&h_r[rA * PO + col0]);
                const float2 hB = *reinterpret_cast<const float2*>(&h_r[rB * PO + col0]);
                *reinterpret_cast<ull*>(&ho_r[rA * PHO + col0]) =
                    pack_ab((1.f - z0) * n[0] + z0 * hA.x, (1.f - z1) * n[1] + z1 * hA.y);
                *reinterpret_cast<ull*>(&ho_r[rB * PHO + col0]) =
                    pack_ab((1.f - z2) * n[2] + z2 * hB.x, (1.f - z3) * n[3] + z3 * hB.y);
            }
        }
    }
    __syncthreads();

    // ---------------- QKV via tf32 mma ----------------
    {
        float acc1[16], acc2[16];
#pragma unroll
        for (int e = 0; e < 16; e++) { acc1[e] = 0.f; acc2[e] = 0.f; }
        if (w < 4) {
            mma_passD(ho_r, PHO, g_qkvF, 0, 12, w, 8 + w, lane, acc1, acc2);
        } else {
            mma_pass1(ho_r, PHO, g_qkvF, 0, 12, w, lane, acc1);
        }

        __syncthreads();   // x_r/h_r fully dead before qkv_s overlay writes

        {
            const int col0 = w * 8 + tg * 2;   // 0..63 (q|k): no bias/relu
#pragma unroll
            for (int mt = 0; mt < 4; mt++) {
                const int rA = mt * 16 + g, rB = rA + 8;
                float* a = acc1 + mt * 4;
                qkv_s[col0 * PT + rA]       = a[0];
                qkv_s[(col0 + 1) * PT + rA] = a[1];
                qkv_s[col0 * PT + rB]       = a[2];
                qkv_s[(col0 + 1) * PT + rB] = a[3];
            }
        }
        if (w < 4) {
            const int col0 = 64 + w * 8 + tg * 2;   // v cols: bias + relu
            const float b0 = vb[col0 - 64], b1 = vb[col0 - 63];
#pragma unroll
            for (int mt = 0; mt < 4; mt++) {
                const int rA = mt * 16 + g, rB = rA + 8;
                float* a = acc2 + mt * 4;
                qkv_s[col0 * PT + rA]       = fmaxf(a[0] + b0, 0.f);
                qkv_s[(col0 + 1) * PT + rA] = fmaxf(a[1] + b1, 0.f);
                qkv_s[col0 * PT + rB]       = fmaxf(a[2] + b0, 0.f);
                qkv_s[(col0 + 1) * PT + rB] = fmaxf(a[3] + b1, 0.f);
            }
        }
    }
    __syncthreads();

    // ---- attention (tid<64) || houtp writeback + decoder h_out-part (rest) --
    if (tid < BM) {
        const int ii = tid & 7;
        const int base = tid & ~7;
        ull sp[4] = {0, 0, 0, 0};
#pragma unroll 8
        for (int a = 0; a < ADIM; a++) {
            ull qa = pack2(qkv_s[a * PT + tid]);
            const ulonglong2 k01 = *reinterpret_cast<const ulonglong2*>(&qkv_s[(32 + a) * PT + base]);
            const ulonglong2 k23 = *reinterpret_cast<const ulonglong2*>(&qkv_s[(32 + a) * PT + base + 4]);
            ffma2(sp[0], k01.x, qa); ffma2(sp[1], k01.y, qa);
            ffma2(sp[2], k23.x, qa); ffma2(sp[3], k23.y, qa);
        }
        float sc[NS];
#pragma unroll
        for (int jp = 0; jp < 4; jp++) {
            float2 v = unpack2(sp[jp]);
            sc[2 * jp]     = v.x * 0.17677669529663689f;
            sc[2 * jp + 1] = v.y * 0.17677669529663689f;
        }
        sc[ii] = -1e9f;
        float mx = -1e30f;
#pragma unroll
        for (int j = 0; j < NS; j++) mx = fmaxf(mx, sc[j]);
        float sum = 0.f;
#pragma unroll
        for (int j = 0; j < NS; j++) { sc[j] = __expf(sc[j] - mx); sum += sc[j]; }
        const float inv = __fdividef(1.f, sum);
        ull wp[4];
#pragma unroll
        for (int jp = 0; jp < 4; jp++)
            wp[jp] = pack_ab(sc[2 * jp] * inv, sc[2 * jp + 1] * inv);
        float xa[ADIM];
#pragma unroll 8
        for (int a = 0; a < ADIM; a++) {
            const ulonglong2 v01 = *reinterpret_cast<const ulonglong2*>(&qkv_s[(64 + a) * PT + base]);
            const ulonglong2 v23 = *reinterpret_cast<const ulonglong2*>(&qkv_s[(64 + a) * PT + base + 4]);
            ull t = 0;
            ffma2(t, v01.x, wp[0]); ffma2(t, v01.y, wp[1]);
            ffma2(t, v23.x, wp[2]); ffma2(t, v23.y, wp[3]);
            xa[a] = hsum2(t);
        }
#pragma unroll
        for (int a4 = 0; a4 < 8; a4++) {
            float4 o = make_float4(xa[a4 * 4], xa[a4 * 4 + 1], xa[a4 * 4 + 2], xa[a4 * 4 + 3]);
            *reinterpret_cast<float4*>(&ho_r[tid * PHO + 64 + a4 * 4]) = o;
        }
    } else {
        // h_out writeback (streaming stores)
        for (int v = tid - BM; v < BM * 16; v += NTHREADS - BM) {
            int r = v >> 4, c4 = (v & 15) * 4;
            float4 t = *reinterpret_cast<const float4*>(&ho_r[r * PHO + c4]);
            __stcs(reinterpret_cast<float4*>(&houtp[(size_t)(rowbase + r) * HDIM + c4]), t);
        }
        // decoder partial: h_out part (k 0..63) + bias -> out_s
        for (int it = tid - BM; it < 448; it += NTHREADS - BM) {
            int pr = it & 31, c = it >> 5;
            const float* hA = &ho_r[(2 * pr) * PHO];
            const float* hB = &ho_r[(2 * pr + 1) * PHO];
            ull acc0 = 0, acc1 = 0;
#pragma unroll 8
            for (int k4 = 0; k4 < 16; k4++) {
                const ulonglong2 wv = *reinterpret_cast<const ulonglong2*>(&g_decP[c * 96 + k4 * 4]);
                const ulonglong2 a4 = *reinterpret_cast<const ulonglong2*>(&hA[k4 * 4]);
                const ulonglong2 b4 = *reinterpret_cast<const ulonglong2*>(&hB[k4 * 4]);
                ffma2(acc0, a4.x, wv.x); ffma2(acc0, a4.y, wv.y);
                ffma2(acc1, b4.x, wv.x); ffma2(acc1, b4.y, wv.y);
            }
            float b = decb[c];
            out_s[(2 * pr) * NACT + c]     = hsum2(acc0) + b;
            out_s[(2 * pr + 1) * NACT + c] = hsum2(acc1) + b;
        }
    }
    __syncthreads();

    // ---------------- decoder xatt part (all threads) + coalesced store -----
    for (int it = tid; it < 448; it += NTHREADS) {
        int pr = it & 31, c = it >> 5;
        const float* xA = &ho_r[(2 * pr) * PHO + 64];
        const float* xB = &ho_r[(2 * pr + 1) * PHO + 64];
        ull acc0 = 0, acc1 = 0;
#pragma unroll 8
        for (int k4 = 0; k4 < 8; k4++) {
            const ulonglong2 wv = *reinterpret_cast<const ulonglong2*>(&g_decP[c * 96 + 64 + k4 * 4]);
            const ulonglong2 a4 = *reinterpret_cast<const ulonglong2*>(&xA[k4 * 4]);
            const ulonglong2 b4 = *reinterpret_cast<const ulonglong2*>(&xB[k4 * 4]);
            ffma2(acc0, a4.x, wv.x); ffma2(acc0, a4.y, wv.y);
            ffma2(acc1, b4.x, wv.x); ffma2(acc1, b4.y, wv.y);
        }
        out_s[(2 * pr) * NACT + c]     += hsum2(acc0);
        out_s[(2 * pr + 1) * NACT + c] += hsum2(acc1);
    }
    __syncthreads();
    {
        float4* dst = reinterpret_cast<float4*>(outp + (size_t)rowbase * NACT);
        const float4* src = reinterpret_cast<const float4*>(out_s);
        for (int v = tid; v < (BM * NACT) / 4; v += NTHREADS)
            __stcs(dst + v, src[v]);
    }
}

extern "C" void kernel_launch(void* const* d_in, const int* in_sizes, int n_in,
                              void* d_out, int out_size)
{
    (void)in_sizes; (void)n_in; (void)out_size;
    const float* obs  = (const float*)d_in[0];
    const float* hid  = (const float*)d_in[1];
    const float* encW = (const float*)d_in[2];
    const float* encb = (const float*)d_in[3];
    const float* Wih  = (const float*)d_in[4];
    const float* Whh  = (const float*)d_in[5];
    const float* bih  = (const float*)d_in[6];
    const float* bhh  = (const float*)d_in[7];
    const float* qW   = (const float*)d_in[8];
    const float* kW   = (const float*)d_in[9];
    const float* vW   = (const float*)d_in[10];
    const float* vb   = (const float*)d_in[11];
    const float* decW = (const float*)d_in[12];
    const float* decb = (const float*)d_in[13];

    float* outp  = (float*)d_out;                 // [B, 14]
    float* houtp = outp + (size_t)BTOT * NACT;    // [B, 64]

    setup_kernel<<<64, 256>>>(encW, Wih, Whh, qW, kW, vW, decW);

    const int smem_bytes = 17408 * sizeof(float); // 69,632 B -> 3 CTAs/SM
    cudaFuncSetAttribute(fused_kernel,
                         cudaFuncAttributeMaxDynamicSharedMemorySize, smem_bytes);
    fused_kernel<<<BTOT / BM, NTHREADS, smem_bytes>>>(
        obs, hid, encb, bih, bhh, vb, decb, outp, houtp);
}